// round 14
// baseline (speedup 1.0000x reference)
#include <cuda_runtime.h>
#include <cuda_fp16.h>
#include <cstdint>

// ============================================================================
// Problem constants
// ============================================================================
static constexpr int M_TOT = 8192;
static constexpr int N_TOT = 4096;
static constexpr int K_TOT = 4096;
static constexpr int GROUP = 128;
static constexpr int NPROF = 8;
static constexpr int GTOT  = N_TOT * K_TOT / GROUP;

// GEMM tiling: CTA 128x128x64, warp tile 64x64 (4 compute warps + 1 producer)
static constexpr int BM = 128;
static constexpr int BN = 128;
static constexpr int BK = 64;
static constexpr int KCH = K_TOT / BK;        // 64
static constexpr int STAGES = 3;

static constexpr int TILE_BYTES  = BM * 128;  // 16384 (A or B tile, swizzled)
static constexpr int STAGE_BYTES = 2 * TILE_BYTES;        // 32768
static constexpr int SMEM_CTRL   = 1024;
static constexpr int SMEM_TOTAL  = SMEM_CTRL + STAGES * STAGE_BYTES;  // 99328 -> 2 CTAs/SM

static constexpr int THREADS = 160;           // 4 compute warps + 1 producer warp

// control offsets (within smem)
static constexpr int SM_FULL0  = 0;   // 3 x 8B
static constexpr int SM_EMPTY0 = 24;  // 3 x 8B

// ============================================================================
// Scratch: pre-swizzled tiles  [blk][kc][row][128B]
// ============================================================================
__device__ __align__(1024) uint32_t g_A[(size_t)(M_TOT / BM) * KCH * 4096];  // 64 MB
__device__ __align__(1024) uint32_t g_B[(size_t)(N_TOT / BN) * KCH * 4096];  // 32 MB

// ============================================================================
// PTX helpers (sm_90-baseline features only: legal at plain sm_103)
// ============================================================================
__device__ __forceinline__ uint32_t smem_u32(const void* p) {
    uint32_t a;
    asm("{ .reg .u64 t; cvta.to.shared.u64 t, %1; cvt.u32.u64 %0, t; }" : "=r"(a) : "l"(p));
    return a;
}
#define MBAR_INIT(addr, cnt) \
    asm volatile("mbarrier.init.shared.b64 [%0], %1;" :: "r"(addr), "r"(cnt) : "memory")
#define MBAR_EXPECT_TX(addr, bytes) \
    asm volatile("mbarrier.arrive.expect_tx.shared.b64 _, [%0], %1;" :: "r"(addr), "r"(bytes) : "memory")
#define MBAR_ARRIVE(addr) \
    asm volatile("mbarrier.arrive.shared.b64 _, [%0];" :: "r"(addr) : "memory")
#define MBAR_WAIT(addr, parity) do {                                              \
    uint32_t _m = (addr), _p = (parity), _d;                                      \
    asm volatile("{\n\t.reg .pred p;\n\t"                                         \
        "mbarrier.try_wait.parity.acquire.cta.shared::cta.b64 p, [%1], %2;\n\t"   \
        "selp.b32 %0, 1, 0, p;\n\t}" : "=r"(_d) : "r"(_m), "r"(_p) : "memory");   \
    if (!_d) {                                                                    \
        asm volatile("{\n\t.reg .pred P1;\n\t"                                    \
            "W%=:\n\t"                                                            \
            "mbarrier.try_wait.parity.acquire.cta.shared::cta.b64 P1, [%0], %1, 0x989680;\n\t" \
            "@P1 bra.uni D%=;\n\t"                                                \
            "bra.uni W%=;\n\t"                                                    \
            "D%=:\n\t}" :: "r"(_m), "r"(_p) : "memory");                          \
    }                                                                             \
} while (0)

__device__ __forceinline__ void bulk_copy(uint32_t dst_smem, const void* src, uint32_t bytes,
                                          uint32_t mbar) {
    asm volatile(
        "cp.async.bulk.shared::cluster.global.mbarrier::complete_tx::bytes [%0], [%1], %2, [%3];"
        :: "r"(dst_smem), "l"(src), "r"(bytes), "r"(mbar) : "memory");
}
#define LDSM_X4(r0, r1, r2, r3, addr)                                              \
    asm volatile("ldmatrix.sync.aligned.m8n8.x4.shared.b16 {%0,%1,%2,%3}, [%4];"   \
                 : "=r"(r0), "=r"(r1), "=r"(r2), "=r"(r3) : "r"(addr))

__device__ __forceinline__ void mma16816(float* c, const uint32_t* a, uint32_t b0, uint32_t b1) {
    asm volatile(
        "mma.sync.aligned.m16n8k16.row.col.f32.f16.f16.f32 "
        "{%0,%1,%2,%3}, {%4,%5,%6,%7}, {%8,%9}, {%0,%1,%2,%3};"
        : "+f"(c[0]), "+f"(c[1]), "+f"(c[2]), "+f"(c[3])
        : "r"(a[0]), "r"(a[1]), "r"(a[2]), "r"(a[3]), "r"(b0), "r"(b1));
}

// ============================================================================
// Fused prep -> pre-swizzled tiles.
// ============================================================================
__global__ void __launch_bounds__(256) prep_kernel(const float* __restrict__ x,
                                                   const float* __restrict__ signs,
                                                   const float* __restrict__ ps,
                                                   const float* __restrict__ routing) {
    const int tid = threadIdx.x;
    if (blockIdx.x < (unsigned)M_TOT) {
        const int m  = blockIdx.x;
        const int mb = m >> 7;
        const int r  = m & 127;
        const float2* __restrict__ xr = (const float2*)(x + (size_t)m * K_TOT);
        const size_t base = (size_t)mb * KCH * 4096;
#pragma unroll
        for (int i = 0; i < 8; i++) {
            const int k2 = i * 256 + tid;
            const int kc = k2 >> 5;
            const int c2 = k2 & 31;
            float2 v = xr[k2];
            __half2 h = __floats2half2_rn(v.x, v.y);
            uint32_t off = (uint32_t)r * 128u + (uint32_t)c2 * 4u;
            uint32_t sw  = off ^ ((off >> 3) & 0x70u);
            g_A[base + (size_t)kc * 4096 + (sw >> 2)] = *reinterpret_cast<uint32_t*>(&h);
        }
    } else {
        __shared__ float s_rt[NPROF];
        __shared__ float s_sc[K_TOT / GROUP];
        const int n = blockIdx.x - M_TOT;
        if (tid < NPROF) s_rt[tid] = routing[tid];
        __syncthreads();
        if (tid < K_TOT / GROUP) {
            const int g = n * (K_TOT / GROUP) + tid;
            float s = 0.f;
#pragma unroll
            for (int p = 0; p < NPROF; p++) s += s_rt[p] * ps[(size_t)p * GTOT + g];
            s_sc[tid] = s;
        }
        __syncthreads();

        const int nb = n >> 7;
        const int r  = n & 127;
        const float2* __restrict__ sr = (const float2*)(signs + (size_t)n * K_TOT);
        const size_t base = (size_t)nb * KCH * 4096;
#pragma unroll
        for (int i = 0; i < 8; i++) {
            const int k2 = i * 256 + tid;
            const int kc = k2 >> 5;
            const int c2 = k2 & 31;
            float sc = s_sc[k2 >> 6];
            float2 s2 = sr[k2];
            __half2 h = __floats2half2_rn(s2.x * sc, s2.y * sc);
            uint32_t off = (uint32_t)r * 128u + (uint32_t)c2 * 4u;
            uint32_t sw  = off ^ ((off >> 3) & 0x70u);
            g_B[base + (size_t)kc * 4096 + (sw >> 2)] = *reinterpret_cast<uint32_t*>(&h);
        }
    }
}

// ============================================================================
// GEMM: warp-specialized mbarrier pipeline.
// Warp 4 = bulk-copy producer; warps 0-3 = HMMA consumers, warp tile 64x64.
// ============================================================================
__global__ void __launch_bounds__(THREADS, 2) gemm_kernel(float* __restrict__ out) {
    extern __shared__ __align__(1024) unsigned char smem[];
    const uint32_t sb = smem_u32(smem);
    const int tid = threadIdx.x;
    const int wid = tid >> 5;
    const int lid = tid & 31;

    const int mBlk = blockIdx.x >> 5;       // 0..63
    const int nBlk = blockIdx.x & 31;       // 0..31

    if (tid == 0) {
#pragma unroll
        for (int s = 0; s < STAGES; s++) {
            MBAR_INIT(sb + SM_FULL0 + s * 8, 1);    // 1 producer thread
            MBAR_INIT(sb + SM_EMPTY0 + s * 8, 4);   // 4 consumer warps
        }
    }
    __syncthreads();

    if (wid == 4) {
        // ---------------- producer: single thread, bulk copies ----------------
        if (lid == 0) {
            const char* gA = (const char*)g_A + (size_t)mBlk * KCH * TILE_BYTES;
            const char* gB = (const char*)g_B + (size_t)nBlk * KCH * TILE_BYTES;
            int st = 0, ph = 1;
            for (int kc = 0; kc < KCH; kc++) {
                MBAR_WAIT(sb + SM_EMPTY0 + st * 8, ph);
                const uint32_t full = sb + SM_FULL0 + st * 8;
                MBAR_EXPECT_TX(full, STAGE_BYTES);
                const uint32_t dst = sb + SMEM_CTRL + st * STAGE_BYTES;
                bulk_copy(dst,              gA + (size_t)kc * TILE_BYTES, TILE_BYTES, full);
                bulk_copy(dst + TILE_BYTES, gB + (size_t)kc * TILE_BYTES, TILE_BYTES, full);
                if (++st == STAGES) { st = 0; ph ^= 1; }
            }
        }
        return;
    }

    // ---------------- consumers: warps 0-3, warp tile 64x64 ----------------
    const int wm = wid >> 1;                // 0..1
    const int wn = wid & 1;                 // 0..1
    const int wmBase = wm * 64;
    const int wnBase = wn * 64;

    int rowOffA[4], xorA[4];
    const int hiA = (lid >> 4) & 1;
#pragma unroll
    for (int mi = 0; mi < 4; mi++) {
        int r = wmBase + mi * 16 + ((lid >> 3) & 1) * 8 + (lid & 7);
        rowOffA[mi] = r * 128;
        xorA[mi] = r & 7;
    }
    int rowOffB[4], xorB[4];
    const int hiB = (lid >> 3) & 1;
#pragma unroll
    for (int g = 0; g < 4; g++) {
        int r = wnBase + g * 16 + ((lid >> 4) & 1) * 8 + (lid & 7);
        rowOffB[g] = r * 128;
        xorB[g] = r & 7;
    }

    float acc[4][8][4];
#pragma unroll
    for (int mi = 0; mi < 4; mi++)
#pragma unroll
        for (int ni = 0; ni < 8; ni++)
#pragma unroll
            for (int j = 0; j < 4; j++) acc[mi][ni][j] = 0.f;

    int st = 0, ph = 0;
    for (int kt = 0; kt < KCH; kt++) {
        MBAR_WAIT(sb + SM_FULL0 + st * 8, ph);
        const uint32_t stA = sb + SMEM_CTRL + st * STAGE_BYTES;
        const uint32_t stB = stA + TILE_BYTES;

#pragma unroll
        for (int ks = 0; ks < 4; ks++) {
            uint32_t a[4][4];
#pragma unroll
            for (int mi = 0; mi < 4; mi++) {
                uint32_t addr = stA + rowOffA[mi] + (((ks * 2 + hiA) ^ xorA[mi]) << 4);
                LDSM_X4(a[mi][0], a[mi][1], a[mi][2], a[mi][3], addr);
            }
            uint32_t b[4][4];
#pragma unroll
            for (int g = 0; g < 4; g++) {
                uint32_t addr = stB + rowOffB[g] + (((ks * 2 + hiB) ^ xorB[g]) << 4);
                LDSM_X4(b[g][0], b[g][1], b[g][2], b[g][3], addr);
            }
#pragma unroll
            for (int mi = 0; mi < 4; mi++)
#pragma unroll
                for (int ni = 0; ni < 8; ni++) {
                    const int g = ni >> 1, sel = (ni & 1) * 2;
                    mma16816(acc[mi][ni], a[mi], b[g][sel], b[g][sel + 1]);
                }
        }

        if (lid == 0) MBAR_ARRIVE(sb + SM_EMPTY0 + st * 8);
        if (++st == STAGES) { st = 0; ph ^= 1; }
    }

    // ---- epilogue: direct fp32 stores ----
    const int mBase = mBlk * BM;
    const int nBase = nBlk * BN;
    const int gr = lid >> 2, tig = lid & 3;
#pragma unroll
    for (int mi = 0; mi < 4; mi++) {
        const int row0 = mBase + wmBase + mi * 16 + gr;
#pragma unroll
        for (int ni = 0; ni < 8; ni++) {
            const int col = nBase + wnBase + ni * 8 + tig * 2;
            float2* p0 = reinterpret_cast<float2*>(out + (size_t)row0 * N_TOT + col);
            float2* p1 = reinterpret_cast<float2*>(out + (size_t)(row0 + 8) * N_TOT + col);
            *p0 = make_float2(acc[mi][ni][0], acc[mi][ni][1]);
            *p1 = make_float2(acc[mi][ni][2], acc[mi][ni][3]);
        }
    }
}

// ============================================================================
// Launch
// ============================================================================
extern "C" void kernel_launch(void* const* d_in, const int* in_sizes, int n_in,
                              void* d_out, int out_size) {
    const float* x       = (const float*)d_in[0];
    const float* signs   = (const float*)d_in[1];
    const float* ps      = (const float*)d_in[2];
    const float* routing = (const float*)d_in[3];
    for (int i = 0; i < n_in; i++) {
        if (in_sizes[i] == M_TOT * K_TOT)      x       = (const float*)d_in[i];
        else if (in_sizes[i] == N_TOT * K_TOT) signs   = (const float*)d_in[i];
        else if (in_sizes[i] == NPROF * GTOT)  ps      = (const float*)d_in[i];
        else if (in_sizes[i] == NPROF)         routing = (const float*)d_in[i];
    }
    float* out = (float*)d_out;

    cudaFuncSetAttribute(gemm_kernel, cudaFuncAttributeMaxDynamicSharedMemorySize, SMEM_TOTAL);

    prep_kernel<<<M_TOT + N_TOT, 256>>>(x, signs, ps, routing);
    gemm_kernel<<<(M_TOT / BM) * (N_TOT / BN), THREADS, SMEM_TOTAL>>>(out);
}

// round 15
// speedup vs baseline: 1.0374x; 1.0374x over previous
#include <cuda_runtime.h>
#include <cuda_fp16.h>
#include <cstdint>

// ============================================================================
// Problem constants
// ============================================================================
static constexpr int M_TOT = 8192;
static constexpr int N_TOT = 4096;
static constexpr int K_TOT = 4096;
static constexpr int GROUP = 128;
static constexpr int NPROF = 8;
static constexpr int GTOT  = N_TOT * K_TOT / GROUP;

// GEMM tiling: CTA 128x128x64, warp tile 32x64 (8 compute warps + 1 producer)
static constexpr int BM = 128;
static constexpr int BN = 128;
static constexpr int BK = 64;
static constexpr int KCH = K_TOT / BK;        // 64
static constexpr int STAGES = 3;

static constexpr int TILE_BYTES  = BM * 128;  // 16384 (A or B tile, swizzled)
static constexpr int STAGE_BYTES = 2 * TILE_BYTES;        // 32768
static constexpr int SMEM_CTRL   = 1024;
static constexpr int SMEM_TOTAL  = SMEM_CTRL + STAGES * STAGE_BYTES;  // 99328 -> 2 CTAs/SM

static constexpr int THREADS = 288;           // 8 compute warps + 1 producer warp

// control offsets (within smem)
static constexpr int SM_FULL0  = 0;   // 3 x 8B
static constexpr int SM_EMPTY0 = 24;  // 3 x 8B

// ============================================================================
// Scratch: pre-swizzled tiles  [blk][kc][row][128B]
// ============================================================================
__device__ __align__(1024) uint32_t g_A[(size_t)(M_TOT / BM) * KCH * 4096];  // 64 MB
__device__ __align__(1024) uint32_t g_B[(size_t)(N_TOT / BN) * KCH * 4096];  // 32 MB

// ============================================================================
// PTX helpers (sm_90-baseline features only: legal at plain sm_103)
// ============================================================================
__device__ __forceinline__ uint32_t smem_u32(const void* p) {
    uint32_t a;
    asm("{ .reg .u64 t; cvta.to.shared.u64 t, %1; cvt.u32.u64 %0, t; }" : "=r"(a) : "l"(p));
    return a;
}
#define MBAR_INIT(addr, cnt) \
    asm volatile("mbarrier.init.shared.b64 [%0], %1;" :: "r"(addr), "r"(cnt) : "memory")
#define MBAR_EXPECT_TX(addr, bytes) \
    asm volatile("mbarrier.arrive.expect_tx.shared.b64 _, [%0], %1;" :: "r"(addr), "r"(bytes) : "memory")
#define MBAR_ARRIVE(addr) \
    asm volatile("mbarrier.arrive.shared.b64 _, [%0];" :: "r"(addr) : "memory")
#define MBAR_WAIT(addr, parity) do {                                              \
    uint32_t _m = (addr), _p = (parity), _d;                                      \
    asm volatile("{\n\t.reg .pred p;\n\t"                                         \
        "mbarrier.try_wait.parity.acquire.cta.shared::cta.b64 p, [%1], %2;\n\t"   \
        "selp.b32 %0, 1, 0, p;\n\t}" : "=r"(_d) : "r"(_m), "r"(_p) : "memory");   \
    if (!_d) {                                                                    \
        asm volatile("{\n\t.reg .pred P1;\n\t"                                    \
            "W%=:\n\t"                                                            \
            "mbarrier.try_wait.parity.acquire.cta.shared::cta.b64 P1, [%0], %1, 0x989680;\n\t" \
            "@P1 bra.uni D%=;\n\t"                                                \
            "bra.uni W%=;\n\t"                                                    \
            "D%=:\n\t}" :: "r"(_m), "r"(_p) : "memory");                          \
    }                                                                             \
} while (0)

__device__ __forceinline__ void bulk_copy(uint32_t dst_smem, const void* src, uint32_t bytes,
                                          uint32_t mbar) {
    asm volatile(
        "cp.async.bulk.shared::cluster.global.mbarrier::complete_tx::bytes [%0], [%1], %2, [%3];"
        :: "r"(dst_smem), "l"(src), "r"(bytes), "r"(mbar) : "memory");
}
#define LDSM_X4(r0, r1, r2, r3, addr)                                              \
    asm volatile("ldmatrix.sync.aligned.m8n8.x4.shared.b16 {%0,%1,%2,%3}, [%4];"   \
                 : "=r"(r0), "=r"(r1), "=r"(r2), "=r"(r3) : "r"(addr))

__device__ __forceinline__ void mma16816(float* c, const uint32_t* a, uint32_t b0, uint32_t b1) {
    asm volatile(
        "mma.sync.aligned.m16n8k16.row.col.f32.f16.f16.f32 "
        "{%0,%1,%2,%3}, {%4,%5,%6,%7}, {%8,%9}, {%0,%1,%2,%3};"
        : "+f"(c[0]), "+f"(c[1]), "+f"(c[2]), "+f"(c[3])
        : "r"(a[0]), "r"(a[1]), "r"(a[2]), "r"(a[3]), "r"(b0), "r"(b1));
}

// ============================================================================
// Fused prep -> pre-swizzled tiles (float4 loads, 8B swizzled stores).
// blocks [0, 8192): x rows -> g_A ; blocks [8192, 12288): W rows -> g_B
// Tile layout: [blk][kc][row 0..127][128B], swizzle off^((off>>3)&0x70).
// ============================================================================
__global__ void __launch_bounds__(256) prep_kernel(const float* __restrict__ x,
                                                   const float* __restrict__ signs,
                                                   const float* __restrict__ ps,
                                                   const float* __restrict__ routing) {
    const int tid = threadIdx.x;
    if (blockIdx.x < (unsigned)M_TOT) {
        const int m  = blockIdx.x;
        const int mb = m >> 7;
        const int r  = m & 127;
        const float4* __restrict__ xr = (const float4*)(x + (size_t)m * K_TOT);
        const size_t base = (size_t)mb * KCH * 4096;
#pragma unroll
        for (int i = 0; i < 4; i++) {
            const int k4 = i * 256 + tid;          // float4 idx within row [0,1024)
            const int kc = k4 >> 4;                // 16 x 8B per 128B chunk row
            const int c4 = k4 & 15;
            float4 v = xr[k4];
            __half2 h0 = __floats2half2_rn(v.x, v.y);
            __half2 h1 = __floats2half2_rn(v.z, v.w);
            uint2 u;
            u.x = *reinterpret_cast<uint32_t*>(&h0);
            u.y = *reinterpret_cast<uint32_t*>(&h1);
            uint32_t off = (uint32_t)r * 128u + (uint32_t)c4 * 8u;
            uint32_t sw  = off ^ ((off >> 3) & 0x70u);
            *reinterpret_cast<uint2*>(&g_A[base + (size_t)kc * 4096 + (sw >> 2)]) = u;
        }
    } else {
        __shared__ float s_rt[NPROF];
        __shared__ float s_sc[K_TOT / GROUP];
        const int n = blockIdx.x - M_TOT;
        if (tid < NPROF) s_rt[tid] = routing[tid];
        __syncthreads();
        if (tid < K_TOT / GROUP) {
            const int g = n * (K_TOT / GROUP) + tid;
            float s = 0.f;
#pragma unroll
            for (int p = 0; p < NPROF; p++) s += s_rt[p] * ps[(size_t)p * GTOT + g];
            s_sc[tid] = s;
        }
        __syncthreads();

        const int nb = n >> 7;
        const int r  = n & 127;
        const float4* __restrict__ sr = (const float4*)(signs + (size_t)n * K_TOT);
        const size_t base = (size_t)nb * KCH * 4096;
#pragma unroll
        for (int i = 0; i < 4; i++) {
            const int k4 = i * 256 + tid;
            const int kc = k4 >> 4;
            const int c4 = k4 & 15;
            float sc = s_sc[k4 >> 5];              // group = (4*k4)/128
            float4 v = sr[k4];
            __half2 h0 = __floats2half2_rn(v.x * sc, v.y * sc);
            __half2 h1 = __floats2half2_rn(v.z * sc, v.w * sc);
            uint2 u;
            u.x = *reinterpret_cast<uint32_t*>(&h0);
            u.y = *reinterpret_cast<uint32_t*>(&h1);
            uint32_t off = (uint32_t)r * 128u + (uint32_t)c4 * 8u;
            uint32_t sw  = off ^ ((off >> 3) & 0x70u);
            *reinterpret_cast<uint2*>(&g_B[base + (size_t)kc * 4096 + (sw >> 2)]) = u;
        }
    }
}

// ============================================================================
// GEMM (identical to the 596us best): warp-specialized mbarrier pipeline.
// Warp 8 = bulk-copy producer; warps 0-7 = HMMA consumers, warp tile 32x64.
// ============================================================================
__global__ void __launch_bounds__(THREADS, 2) gemm_kernel(float* __restrict__ out) {
    extern __shared__ __align__(1024) unsigned char smem[];
    const uint32_t sb = smem_u32(smem);
    const int tid = threadIdx.x;
    const int wid = tid >> 5;
    const int lid = tid & 31;

    const int mBlk = blockIdx.x >> 5;       // 0..63
    const int nBlk = blockIdx.x & 31;       // 0..31

    if (tid == 0) {
#pragma unroll
        for (int s = 0; s < STAGES; s++) {
            MBAR_INIT(sb + SM_FULL0 + s * 8, 1);    // 1 producer thread
            MBAR_INIT(sb + SM_EMPTY0 + s * 8, 8);   // 8 consumer warps
        }
    }
    __syncthreads();

    if (wid == 8) {
        if (lid == 0) {
            const char* gA = (const char*)g_A + (size_t)mBlk * KCH * TILE_BYTES;
            const char* gB = (const char*)g_B + (size_t)nBlk * KCH * TILE_BYTES;
            int st = 0, ph = 1;
            for (int kc = 0; kc < KCH; kc++) {
                MBAR_WAIT(sb + SM_EMPTY0 + st * 8, ph);
                const uint32_t full = sb + SM_FULL0 + st * 8;
                MBAR_EXPECT_TX(full, STAGE_BYTES);
                const uint32_t dst = sb + SMEM_CTRL + st * STAGE_BYTES;
                bulk_copy(dst,              gA + (size_t)kc * TILE_BYTES, TILE_BYTES, full);
                bulk_copy(dst + TILE_BYTES, gB + (size_t)kc * TILE_BYTES, TILE_BYTES, full);
                if (++st == STAGES) { st = 0; ph ^= 1; }
            }
        }
        return;
    }

    // ---------------- consumers: warps 0-7, warp tile 32x64 ----------------
    const int wm = wid >> 1;                // 0..3
    const int wn = wid & 1;                 // 0..1
    const int wmBase = wm * 32;
    const int wnBase = wn * 64;

    int rowOffA[2], xorA[2];
    const int hiA = (lid >> 4) & 1;
#pragma unroll
    for (int mi = 0; mi < 2; mi++) {
        int r = wmBase + mi * 16 + ((lid >> 3) & 1) * 8 + (lid & 7);
        rowOffA[mi] = r * 128;
        xorA[mi] = r & 7;
    }
    int rowOffB[4], xorB[4];
    const int hiB = (lid >> 3) & 1;
#pragma unroll
    for (int g = 0; g < 4; g++) {
        int r = wnBase + g * 16 + ((lid >> 4) & 1) * 8 + (lid & 7);
        rowOffB[g] = r * 128;
        xorB[g] = r & 7;
    }

    float acc[2][8][4];
#pragma unroll
    for (int mi = 0; mi < 2; mi++)
#pragma unroll
        for (int ni = 0; ni < 8; ni++)
#pragma unroll
            for (int j = 0; j < 4; j++) acc[mi][ni][j] = 0.f;

    int st = 0, ph = 0;
    for (int kt = 0; kt < KCH; kt++) {
        MBAR_WAIT(sb + SM_FULL0 + st * 8, ph);
        const uint32_t stA = sb + SMEM_CTRL + st * STAGE_BYTES;
        const uint32_t stB = stA + TILE_BYTES;

#pragma unroll
        for (int ks = 0; ks < 4; ks++) {
            uint32_t a[2][4];
#pragma unroll
            for (int mi = 0; mi < 2; mi++) {
                uint32_t addr = stA + rowOffA[mi] + (((ks * 2 + hiA) ^ xorA[mi]) << 4);
                LDSM_X4(a[mi][0], a[mi][1], a[mi][2], a[mi][3], addr);
            }
            uint32_t b[4][4];
#pragma unroll
            for (int g = 0; g < 4; g++) {
                uint32_t addr = stB + rowOffB[g] + (((ks * 2 + hiB) ^ xorB[g]) << 4);
                LDSM_X4(b[g][0], b[g][1], b[g][2], b[g][3], addr);
            }
#pragma unroll
            for (int mi = 0; mi < 2; mi++)
#pragma unroll
                for (int ni = 0; ni < 8; ni++) {
                    const int g = ni >> 1, sel = (ni & 1) * 2;
                    mma16816(acc[mi][ni], a[mi], b[g][sel], b[g][sel + 1]);
                }
        }

        if (lid == 0) MBAR_ARRIVE(sb + SM_EMPTY0 + st * 8);
        if (++st == STAGES) { st = 0; ph ^= 1; }
    }

    // ---- epilogue: direct fp32 stores ----
    const int mBase = mBlk * BM;
    const int nBase = nBlk * BN;
    const int gr = lid >> 2, tig = lid & 3;
#pragma unroll
    for (int mi = 0; mi < 2; mi++) {
        const int row0 = mBase + wmBase + mi * 16 + gr;
#pragma unroll
        for (int ni = 0; ni < 8; ni++) {
            const int col = nBase + wnBase + ni * 8 + tig * 2;
            float2* p0 = reinterpret_cast<float2*>(out + (size_t)row0 * N_TOT + col);
            float2* p1 = reinterpret_cast<float2*>(out + (size_t)(row0 + 8) * N_TOT + col);
            *p0 = make_float2(acc[mi][ni][0], acc[mi][ni][1]);
            *p1 = make_float2(acc[mi][ni][2], acc[mi][ni][3]);
        }
    }
}

// ============================================================================
// Launch
// ============================================================================
extern "C" void kernel_launch(void* const* d_in, const int* in_sizes, int n_in,
                              void* d_out, int out_size) {
    const float* x       = (const float*)d_in[0];
    const float* signs   = (const float*)d_in[1];
    const float* ps      = (const float*)d_in[2];
    const float* routing = (const float*)d_in[3];
    for (int i = 0; i < n_in; i++) {
        if (in_sizes[i] == M_TOT * K_TOT)      x       = (const float*)d_in[i];
        else if (in_sizes[i] == N_TOT * K_TOT) signs   = (const float*)d_in[i];
        else if (in_sizes[i] == NPROF * GTOT)  ps      = (const float*)d_in[i];
        else if (in_sizes[i] == NPROF)         routing = (const float*)d_in[i];
    }
    float* out = (float*)d_out;

    cudaFuncSetAttribute(gemm_kernel, cudaFuncAttributeMaxDynamicSharedMemorySize, SMEM_TOTAL);

    prep_kernel<<<M_TOT + N_TOT, 256>>>(x, signs, ps, routing);
    gemm_kernel<<<(M_TOT / BM) * (N_TOT / BN), THREADS, SMEM_TOTAL>>>(out);
}